// round 1
// baseline (speedup 1.0000x reference)
#include <cuda_runtime.h>
#include <cstdint>

#define NN   4096
#define DD   16
#define BB   32
#define CI   32
#define CO   32
#define JTOT (BB*CI)     // 1024
#define KIO  (2*CI*CO)   // 2048

// ---------------- scratch (device globals: allocation-free) ----------------
__device__ float g_P[(size_t)NN*NN];      // 64MB  unnormalized exp(relu(E E^T))
__device__ float g_rinv[NN];              // 1/rowsum
__device__ float g_Y[(size_t)NN*JTOT];    // 16MB  P @ X   (unnormalized)
__device__ float g_W[(size_t)NN*KIO];     // 32MB  per-node weights [n][k][i][o]

// ---------------- fast exp for v >= 0 (FFMA only, no MUFU) ----------------
__device__ __forceinline__ float fast_exp_pos(float v) {
    // exp(v) = 2^(v*log2e), v in [0, ~60]
    float y = v * 1.4426950408889634f;
    int   i = (int)y;                 // v>=0 -> trunc == floor
    float f = y - (float)i;           // [0,1)
    // degree-7 Taylor of 2^f (max rel err ~7e-7), exact 1.0 at f=0
    float p = 1.5252733804059838e-5f;
    p = fmaf(p, f, 1.5403530393381608e-4f);
    p = fmaf(p, f, 1.3333558146428443e-3f);
    p = fmaf(p, f, 9.6181291076284772e-3f);
    p = fmaf(p, f, 5.5504108664821580e-2f);
    p = fmaf(p, f, 2.4022650695910071e-1f);
    p = fmaf(p, f, 6.9314718055994531e-1f);
    p = fmaf(p, f, 1.0f);
    return p * __int_as_float((i + 127) << 23);
}

// ---------------- kernel 1: P = exp(relu(E E^T)), rinv = 1/rowsum ----------
__global__ void __launch_bounds__(256) k_supports(const float* __restrict__ E) {
    __shared__ float es[4][DD];
    __shared__ float wsum[4][8];
    const int tid = threadIdx.x;
    const int n0  = blockIdx.x * 4;

    if (tid < 4*DD) es[tid >> 4][tid & 15] = E[n0*DD + tid];
    __syncthreads();

    // copy the 4 query rows into registers (64 regs)
    float ereg[4][DD];
    #pragma unroll
    for (int r = 0; r < 4; r++)
        #pragma unroll
        for (int d = 0; d < DD; d++) ereg[r][d] = es[r][d];

    float sum[4] = {0.f, 0.f, 0.f, 0.f};

    for (int m = tid; m < NN; m += 256) {
        const float4* em4 = reinterpret_cast<const float4*>(E + (size_t)m*DD);
        float4 q0 = em4[0], q1 = em4[1], q2 = em4[2], q3 = em4[3];
        float av[DD] = {q0.x,q0.y,q0.z,q0.w, q1.x,q1.y,q1.z,q1.w,
                        q2.x,q2.y,q2.z,q2.w, q3.x,q3.y,q3.z,q3.w};
        #pragma unroll
        for (int r = 0; r < 4; r++) {
            float d = 0.f;
            #pragma unroll
            for (int t = 0; t < DD; t++) d = fmaf(av[t], ereg[r][t], d);
            d = fmaxf(d, 0.f);
            float p = fast_exp_pos(d);
            g_P[(size_t)(n0 + r)*NN + m] = p;
            sum[r] += p;
        }
    }

    #pragma unroll
    for (int r = 0; r < 4; r++) {
        float s = sum[r];
        #pragma unroll
        for (int o = 16; o > 0; o >>= 1) s += __shfl_xor_sync(0xffffffffu, s, o);
        if ((tid & 31) == 0) wsum[r][tid >> 5] = s;
    }
    __syncthreads();
    if (tid < 4) {
        float t = 0.f;
        #pragma unroll
        for (int w = 0; w < 8; w++) t += wsum[tid][w];
        g_rinv[n0 + tid] = 1.0f / t;
    }
}

// ---------------- kernel 2: Y[4096,1024] = P[4096,4096] @ X[4096,1024] -----
// B operand read directly from x: B[m][j] = x[(j>>5)*NN*CI + m*CI + (j&31)]
// Uses packed fma.rn.f32x2 (FFMA2) -> full-rate fp32.
#define BM 128
#define BN 64
#define BKK 16
#define APAD 130   // pad so transposed STS is conflict-free and f32x2 LDS stays 8B aligned

union F2 { float2 f; unsigned long long u; };

__global__ void __launch_bounds__(256) k_gemm(const float* __restrict__ x) {
    __shared__ __align__(16) float as[BKK * APAD];  // as[k][row], padded
    __shared__ __align__(16) float bs[BKK * BN];    // bs[k][j]

    const int tid  = threadIdx.x;
    const int tx   = tid & 15;        // 16 col-groups of 4
    const int ty   = tid >> 4;        // 16 row-groups of 8
    const int n0   = blockIdx.y * BM;
    const int col0 = blockIdx.x * BN;

    // global-load mapping
    const int ar = tid >> 2;          // 0..63 (row), also +64
    const int ac = (tid & 3) * 4;     // k offset 0,4,8,12
    const int bk = tid >> 4;          // 0..15 (k)
    const int bj = (tid & 15) * 4;    // 0..60 (j)

    const float* aptr0 = g_P + (size_t)(n0 + ar)      * NN + ac;
    const float* aptr1 = g_P + (size_t)(n0 + ar + 64) * NN + ac;
    const int    colg  = col0 + bj;
    const float* bptr  = x + (size_t)(colg >> 5) * (size_t)NN * CI + (colg & 31);

    F2 c[4][4];
    #pragma unroll
    for (int ip = 0; ip < 4; ip++)
        #pragma unroll
        for (int j = 0; j < 4; j++) c[ip][j].u = 0ull;

    // prefetch iter 0
    float4 ra0 = *reinterpret_cast<const float4*>(aptr0);
    float4 ra1 = *reinterpret_cast<const float4*>(aptr1);
    float4 rb  = *reinterpret_cast<const float4*>(bptr + (size_t)bk * CI);

    for (int k0 = 0; k0 < NN; k0 += BKK) {
        __syncthreads();
        // store (A transposed)
        as[(ac+0)*APAD + ar]      = ra0.x;
        as[(ac+1)*APAD + ar]      = ra0.y;
        as[(ac+2)*APAD + ar]      = ra0.z;
        as[(ac+3)*APAD + ar]      = ra0.w;
        as[(ac+0)*APAD + ar + 64] = ra1.x;
        as[(ac+1)*APAD + ar + 64] = ra1.y;
        as[(ac+2)*APAD + ar + 64] = ra1.z;
        as[(ac+3)*APAD + ar + 64] = ra1.w;
        *reinterpret_cast<float4*>(&bs[bk*BN + bj]) = rb;
        __syncthreads();

        if (k0 + BKK < NN) {   // prefetch next tile (overlaps compute)
            ra0 = *reinterpret_cast<const float4*>(aptr0 + k0 + BKK);
            ra1 = *reinterpret_cast<const float4*>(aptr1 + k0 + BKK);
            rb  = *reinterpret_cast<const float4*>(bptr + (size_t)(k0 + BKK + bk) * CI);
        }

        #pragma unroll
        for (int kk = 0; kk < BKK; kk++) {
            F2 a[4];
            const float2* ap = reinterpret_cast<const float2*>(&as[kk*APAD + ty*8]);
            a[0].f = ap[0]; a[1].f = ap[1]; a[2].f = ap[2]; a[3].f = ap[3];
            F2 bd[4];
            #pragma unroll
            for (int j = 0; j < 4; j++) {
                float bv = bs[kk*BN + tx*4 + j];
                asm("mov.b64 %0, {%1, %1};" : "=l"(bd[j].u) : "f"(bv));
            }
            #pragma unroll
            for (int ip = 0; ip < 4; ip++)
                #pragma unroll
                for (int j = 0; j < 4; j++)
                    asm("fma.rn.f32x2 %0, %1, %2, %0;"
                        : "+l"(c[ip][j].u) : "l"(a[ip].u), "l"(bd[j].u));
        }
    }

    // epilogue: rows ty*8 + 2ip (+1), cols col0 + tx*4 + j
    #pragma unroll
    for (int ip = 0; ip < 4; ip++) {
        const int row = n0 + ty*8 + ip*2;
        float4 lo = make_float4(c[ip][0].f.x, c[ip][1].f.x, c[ip][2].f.x, c[ip][3].f.x);
        float4 hi = make_float4(c[ip][0].f.y, c[ip][1].f.y, c[ip][2].f.y, c[ip][3].f.y);
        *reinterpret_cast<float4*>(&g_Y[(size_t)row      * JTOT + col0 + tx*4]) = lo;
        *reinterpret_cast<float4*>(&g_Y[(size_t)(row+1)  * JTOT + col0 + tx*4]) = hi;
    }
}

// ---------------- kernel 3: W[n][kio] = sum_d E[n][d] * wp[d][kio] ---------
__global__ void __launch_bounds__(256) k_wgen(const float* __restrict__ E,
                                              const float* __restrict__ wp) {
    const int col = blockIdx.x * 256 + threadIdx.x;   // 0..2047
    const int n0  = blockIdx.y * 128;
    __shared__ float es[128 * DD];
    for (int t = threadIdx.x; t < 128*DD; t += 256) es[t] = E[n0*DD + t];
    float w[DD];
    #pragma unroll
    for (int d = 0; d < DD; d++) w[d] = wp[d*KIO + col];
    __syncthreads();
    #pragma unroll 4
    for (int n = 0; n < 128; n++) {
        float acc = 0.f;
        #pragma unroll
        for (int d = 0; d < DD; d++) acc = fmaf(es[n*DD + d], w[d], acc);
        g_W[(size_t)(n0 + n)*KIO + col] = acc;
    }
}

// ---------------- kernel 4: epilogue -------------------------------------
// out[b,n,o] = sum_i x[b,n,i]*W[n,0,i,o] + rinv[n]*sum_i Y[n,b*32+i]*W[n,1,i,o] + bias[n,o]
__global__ void __launch_bounds__(256) k_out(const float* __restrict__ x,
                                             const float* __restrict__ bp,
                                             const float* __restrict__ E,
                                             float* __restrict__ out) {
    const int n   = blockIdx.x;
    const int tid = threadIdx.x;
    __shared__ float ws[KIO];    // 8KB
    __shared__ float xs[JTOT];   // 4KB  xs[b*32+i]
    __shared__ float ys[JTOT];   // 4KB
    __shared__ float bsh[CO];

    for (int t = tid; t < KIO; t += 256) ws[t] = g_W[(size_t)n*KIO + t];
    for (int t = tid; t < JTOT; t += 256) {
        int b = t >> 5, i = t & 31;
        xs[t] = x[(size_t)b*NN*CI + (size_t)n*CI + i];
        ys[t] = g_Y[(size_t)n*JTOT + t];
    }
    if (tid < CO) {
        float acc = 0.f;
        #pragma unroll
        for (int d = 0; d < DD; d++) acc = fmaf(E[n*DD + d], bp[d*CO + tid], acc);
        bsh[tid] = acc;
    }
    __syncthreads();

    const float rinv = g_rinv[n];
    const int o  = tid & 31;
    const int b0 = tid >> 5;
    #pragma unroll
    for (int v = 0; v < 4; v++) {
        const int b = b0 + v*8;
        float a0 = 0.f, a1 = 0.f;
        #pragma unroll
        for (int i = 0; i < CI; i++) {
            a0 = fmaf(xs[b*32 + i], ws[i*32 + o],        a0);
            a1 = fmaf(ys[b*32 + i], ws[1024 + i*32 + o], a1);
        }
        out[(size_t)b*NN*CO + (size_t)n*CO + o] = fmaf(rinv, a1, a0) + bsh[o];
    }
}

// ---------------- launcher -------------------------------------------------
extern "C" void kernel_launch(void* const* d_in, const int* in_sizes, int n_in,
                              void* d_out, int out_size) {
    const float* x  = (const float*)d_in[0];   // [32,4096,32]
    const float* wp = (const float*)d_in[1];   // [16,2,32,32]
    const float* bp = (const float*)d_in[2];   // [16,32]
    const float* E  = (const float*)d_in[3];   // [4096,16]
    float* out = (float*)d_out;                // [32,4096,32]

    k_supports<<<NN/4, 256>>>(E);
    dim3 gg(JTOT/BN, NN/BM);                   // (16, 32)
    k_gemm<<<gg, 256>>>(x);
    dim3 gw(KIO/256, NN/128);                  // (8, 32)
    k_wgen<<<gw, 256>>>(E, wp);
    k_out<<<NN, 256>>>(x, bp, E, out);
}

// round 3
// speedup vs baseline: 2.7308x; 2.7308x over previous
#include <cuda_runtime.h>
#include <cstdint>

#define NN   4096
#define DD   16
#define BB   32
#define CI   32
#define CO   32
#define JTOT (BB*CI)     // 1024
#define KIO  (2*CI*CO)   // 2048

// ---------------- scratch ----------------
__device__ float g_P [(size_t)NN*NN];     // 64MB  tf32-rounded exp(relu(E E^T))
__device__ float g_rinv[NN];
__device__ float g_Y [(size_t)NN*JTOT];   // 16MB  P @ X (unnormalized)
__device__ float g_W [(size_t)NN*KIO];    // 32MB
__device__ float g_Xt[(size_t)JTOT*NN];   // 16MB  Xt[j][m] = tf32(x[b,m,c]), j=b*32+c

// ---------------- helpers ----------------
__device__ __forceinline__ uint32_t smem_u32(const void* p) {
    uint32_t a;
    asm("{ .reg .u64 t; cvta.to.shared.u64 t, %1; cvt.u32.u64 %0, t; }" : "=r"(a) : "l"(p));
    return a;
}
__device__ __forceinline__ float to_tf32(float v) {
    uint32_t u; asm("cvt.rna.tf32.f32 %0, %1;" : "=r"(u) : "f"(v));
    return __uint_as_float(u);
}
__device__ __forceinline__ float fast_exp_pos(float v) {
    float y = v * 1.4426950408889634f;
    int   i = (int)y;
    float f = y - (float)i;
    float p = 1.5252733804059838e-5f;
    p = fmaf(p, f, 1.5403530393381608e-4f);
    p = fmaf(p, f, 1.3333558146428443e-3f);
    p = fmaf(p, f, 9.6181291076284772e-3f);
    p = fmaf(p, f, 5.5504108664821580e-2f);
    p = fmaf(p, f, 2.4022650695910071e-1f);
    p = fmaf(p, f, 6.9314718055994531e-1f);
    p = fmaf(p, f, 1.0f);
    return p * __int_as_float((i + 127) << 23);
}
union F2 { float2 f; unsigned long long u; };
__device__ __forceinline__ F2 dup2(float v) { F2 r; asm("mov.b64 %0, {%1, %1};" : "=l"(r.u) : "f"(v)); return r; }
__device__ __forceinline__ void fma2(F2& c, F2 a, F2 b) {
    asm("fma.rn.f32x2 %0, %1, %2, %0;" : "+l"(c.u) : "l"(a.u), "l"(b.u));
}
__device__ __forceinline__ void cp16(uint32_t dst, const float* src) {
    asm volatile("cp.async.cg.shared.global [%0], [%1], 16;" :: "r"(dst), "l"(src));
}
__device__ __forceinline__ uint2 lds64(uint32_t addr) {
    uint2 v;
    asm volatile("ld.shared.v2.b32 {%0, %1}, [%2];" : "=r"(v.x), "=r"(v.y) : "r"(addr));
    return v;
}
__device__ __forceinline__ void mma_tf32(float* c, const uint32_t* a, const uint32_t* b) {
    asm volatile(
        "mma.sync.aligned.m16n8k8.row.col.f32.tf32.tf32.f32 "
        "{%0,%1,%2,%3}, {%4,%5,%6,%7}, {%8,%9}, {%0,%1,%2,%3};"
        : "+f"(c[0]), "+f"(c[1]), "+f"(c[2]), "+f"(c[3])
        : "r"(a[0]), "r"(a[1]), "r"(a[2]), "r"(a[3]), "r"(b[0]), "r"(b[1]));
}
#define SWZ128(off) ((off) ^ (((off) >> 3) & 0x70))

// ---------------- kernel 1: P = tf32(exp(relu(E E^T))), rinv ----------
__global__ void __launch_bounds__(256) k_supports(const float* __restrict__ E) {
    __shared__ float es[4][DD];
    __shared__ float wsum[4][8];
    const int tid = threadIdx.x;
    const int n0  = blockIdx.x * 4;

    if (tid < 4*DD) es[tid >> 4][tid & 15] = E[n0*DD + tid];
    __syncthreads();
    float ereg[4][DD];
    #pragma unroll
    for (int r = 0; r < 4; r++)
        #pragma unroll
        for (int d = 0; d < DD; d++) ereg[r][d] = es[r][d];

    float sum[4] = {0.f, 0.f, 0.f, 0.f};
    for (int m = tid; m < NN; m += 256) {
        const float4* em4 = reinterpret_cast<const float4*>(E + (size_t)m*DD);
        float4 q0 = em4[0], q1 = em4[1], q2 = em4[2], q3 = em4[3];
        float av[DD] = {q0.x,q0.y,q0.z,q0.w, q1.x,q1.y,q1.z,q1.w,
                        q2.x,q2.y,q2.z,q2.w, q3.x,q3.y,q3.z,q3.w};
        #pragma unroll
        for (int r = 0; r < 4; r++) {
            float d = 0.f;
            #pragma unroll
            for (int t = 0; t < DD; t++) d = fmaf(av[t], ereg[r][t], d);
            d = fmaxf(d, 0.f);
            float p = to_tf32(fast_exp_pos(d));
            g_P[(size_t)(n0 + r)*NN + m] = p;
            sum[r] += p;
        }
    }
    #pragma unroll
    for (int r = 0; r < 4; r++) {
        float s = sum[r];
        #pragma unroll
        for (int o = 16; o > 0; o >>= 1) s += __shfl_xor_sync(0xffffffffu, s, o);
        if ((tid & 31) == 0) wsum[r][tid >> 5] = s;
    }
    __syncthreads();
    if (tid < 4) {
        float t = 0.f;
        #pragma unroll
        for (int w = 0; w < 8; w++) t += wsum[tid][w];
        g_rinv[n0 + tid] = 1.0f / t;
    }
}

// ---------------- kernel 1b: Xt[j][m] = tf32(x[b,m,c]) ----------------
__global__ void __launch_bounds__(256) k_tr(const float* __restrict__ x) {
    __shared__ float s[32*33];
    const int tid = threadIdx.x;
    const int b   = blockIdx.y;
    const int m0  = blockIdx.x * 32;
    #pragma unroll
    for (int q = 0; q < 4; q++) {
        int idx = tid + q*256;
        int m = idx >> 5, c = idx & 31;
        s[c*33 + m] = to_tf32(x[(size_t)b*NN*CI + (size_t)(m0 + m)*CI + c]);
    }
    __syncthreads();
    #pragma unroll
    for (int q = 0; q < 4; q++) {
        int idx = tid + q*256;
        int jl = idx >> 5, mo = idx & 31;
        g_Xt[(size_t)(b*32 + jl)*NN + m0 + mo] = s[jl*33 + mo];
    }
}

// ---------------- kernel 2: mma.sync tf32 GEMM  Y = P @ Xt^T ----------------
// CTA 128x256, BK=32, 4-stage cp.async. 8 warps (2x4), warp tile 64x64.
#define NITER   (NN/32)          // 128
#define STAGEB  49152            // 16KB A + 32KB B
#define SM_DATA 1024
#define GSMEM   (SM_DATA + 4*STAGEB)   // 197632

__device__ __forceinline__ void issue_loads(uint32_t sbase, int stage, int n0, int col0,
                                            int k0, int tid) {
    const uint32_t sa = sbase + SM_DATA + stage*STAGEB;
    const uint32_t sb = sa + 16384;
    #pragma unroll
    for (int q = 0; q < 4; q++) {                      // A: 128 rows x 32 k
        int gid = tid + q*256;
        int row = gid >> 3, g = gid & 7;
        uint32_t off = row*128 + g*16;
        cp16(sa + SWZ128(off), g_P + (size_t)(n0 + row)*NN + k0 + g*4);
    }
    #pragma unroll
    for (int q = 0; q < 8; q++) {                      // B: 256 rows x 32 k
        int gid = tid + q*256;
        int row = gid >> 3, g = gid & 7;
        uint32_t off = row*128 + g*16;
        cp16(sb + SWZ128(off), g_Xt + (size_t)(col0 + row)*NN + k0 + g*4);
    }
    asm volatile("cp.async.commit_group;" ::: "memory");
}

__global__ void __launch_bounds__(256, 1) k_gemm() {
    extern __shared__ __align__(1024) uint8_t dsm[];
    const uint32_t sbase = smem_u32(dsm);
    const int tid  = threadIdx.x;
    const int wid  = tid >> 5;
    const int lane = tid & 31;
    const int col0 = blockIdx.x * 256;
    const int n0   = blockIdx.y * 128;

    const int wm = (wid >> 2) * 64;        // 0 / 64
    const int wn = (wid & 3) * 64;         // 0..192
    const int r   = lane >> 2;             // 0..7
    const int kg  = lane & 3;              // 0..3
    const int kgh = kg >> 1;               // 0..1
    const uint32_t lowoff = (kg & 1) * 8;

    // stage-relative fragment addresses
    uint32_t relA[8];  uint32_t mswA[4];
    #pragma unroll
    for (int t = 0; t < 4; t++) {
        int m = wm + t*16 + r;
        relA[t*2]   = (uint32_t)(m*128)       + lowoff;
        relA[t*2+1] = (uint32_t)((m+8)*128)   + lowoff;
        mswA[t]     = (uint32_t)((m & 7) << 4);        // (m&7) == ((m+8)&7)
    }
    uint32_t relB[8];  uint32_t mswB[8];
    #pragma unroll
    for (int nt = 0; nt < 8; nt++) {
        int j = wn + nt*8 + r;
        relB[nt] = (uint32_t)(j*128) + 16384u + lowoff;
        mswB[nt] = (uint32_t)((j & 7) << 4);
    }

    float acc[4][8][4];
    #pragma unroll
    for (int t = 0; t < 4; t++)
        #pragma unroll
        for (int nt = 0; nt < 8; nt++)
            #pragma unroll
            for (int e = 0; e < 4; e++) acc[t][nt][e] = 0.f;

    issue_loads(sbase, 0, n0, col0, 0,  tid);
    issue_loads(sbase, 1, n0, col0, 32, tid);
    issue_loads(sbase, 2, n0, col0, 64, tid);

    for (int i = 0; i < NITER; i++) {
        asm volatile("cp.async.wait_group 2;" ::: "memory");
        __syncthreads();
        issue_loads(sbase, (i + 3) & 3, n0, col0, ((i + 3) & (NITER-1))*32, tid);

        const uint32_t cur = sbase + SM_DATA + (i & 3)*STAGEB;
        #pragma unroll
        for (int ks = 0; ks < 4; ks++) {
            const uint32_t Koff = (uint32_t)((ks*2 + kgh) << 4);
            uint32_t a[4][4];
            #pragma unroll
            for (int t = 0; t < 4; t++) {
                uint2 v0 = lds64(cur + relA[t*2]   + (Koff ^ mswA[t]));
                uint2 v1 = lds64(cur + relA[t*2+1] + (Koff ^ mswA[t]));
                a[t][0] = v0.x; a[t][1] = v1.x; a[t][2] = v0.y; a[t][3] = v1.y;
            }
            uint32_t b[8][2];
            #pragma unroll
            for (int nt = 0; nt < 8; nt++) {
                uint2 w = lds64(cur + relB[nt] + (Koff ^ mswB[nt]));
                b[nt][0] = w.x; b[nt][1] = w.y;
            }
            #pragma unroll
            for (int t = 0; t < 4; t++)
                #pragma unroll
                for (int nt = 0; nt < 8; nt++)
                    mma_tf32(acc[t][nt], a[t], b[nt]);
        }
    }

    // epilogue: direct float2 stores to g_Y
    #pragma unroll
    for (int t = 0; t < 4; t++) {
        const int row = n0 + wm + t*16 + r;
        #pragma unroll
        for (int nt = 0; nt < 8; nt++) {
            const int col = col0 + wn + nt*8 + kg*2;
            *reinterpret_cast<float2*>(&g_Y[(size_t)row*JTOT + col]) =
                make_float2(acc[t][nt][0], acc[t][nt][1]);
            *reinterpret_cast<float2*>(&g_Y[(size_t)(row+8)*JTOT + col]) =
                make_float2(acc[t][nt][2], acc[t][nt][3]);
        }
    }
}

// ---------------- kernel 3: W[n][kio] = sum_d E[n][d] * wp[d][kio] ---------
__global__ void __launch_bounds__(256) k_wgen(const float* __restrict__ E,
                                              const float* __restrict__ wp) {
    const int col = blockIdx.x * 256 + threadIdx.x;
    const int n0  = blockIdx.y * 128;
    __shared__ float es[128 * DD];
    for (int t = threadIdx.x; t < 128*DD; t += 256) es[t] = E[n0*DD + t];
    float w[DD];
    #pragma unroll
    for (int d = 0; d < DD; d++) w[d] = wp[d*KIO + col];
    __syncthreads();
    #pragma unroll 4
    for (int n = 0; n < 128; n++) {
        float acc = 0.f;
        #pragma unroll
        for (int d = 0; d < DD; d++) acc = fmaf(es[n*DD + d], w[d], acc);
        g_W[(size_t)(n0 + n)*KIO + col] = acc;
    }
}

// ---------------- kernel 4: epilogue (f32x2, 4 chains) ---------------------
__global__ void __launch_bounds__(256) k_out(const float* __restrict__ x,
                                             const float* __restrict__ bp,
                                             const float* __restrict__ E,
                                             float* __restrict__ out) {
    const int n   = blockIdx.x;
    const int tid = threadIdx.x;
    __shared__ __align__(16) float ws[KIO];
    __shared__ __align__(16) float xs[JTOT];
    __shared__ __align__(16) float ys[JTOT];
    __shared__ float bsh[CO];

    {
        const float4* wsrc = reinterpret_cast<const float4*>(&g_W[(size_t)n*KIO]);
        float4* wdst = reinterpret_cast<float4*>(ws);
        wdst[tid]       = wsrc[tid];
        wdst[tid + 256] = wsrc[tid + 256];
        const float4* ysrc = reinterpret_cast<const float4*>(&g_Y[(size_t)n*JTOT]);
        reinterpret_cast<float4*>(ys)[tid] = ysrc[tid];
    }
    for (int t = tid; t < JTOT; t += 256) {
        int b = t >> 5, i = t & 31;
        xs[t] = x[(size_t)b*NN*CI + (size_t)n*CI + i];
    }
    if (tid < CO) {
        float acc = 0.f;
        #pragma unroll
        for (int d = 0; d < DD; d++) acc = fmaf(E[n*DD + d], bp[d*CO + tid], acc);
        bsh[tid] = acc;
    }
    __syncthreads();

    const float rinv = g_rinv[n];
    const int o2 = tid & 15;
    const int bq = tid >> 4;
    #pragma unroll
    for (int rep = 0; rep < 2; rep++) {
        const int b = bq + rep*16;
        F2 cx0, cx1, cy0, cy1;
        cx0.u = cx1.u = cy0.u = cy1.u = 0ull;
        #pragma unroll
        for (int i = 0; i < CI; i += 2) {
            F2 xv0 = dup2(xs[b*32 + i]);
            F2 xv1 = dup2(xs[b*32 + i + 1]);
            F2 yv0 = dup2(ys[b*32 + i]);
            F2 yv1 = dup2(ys[b*32 + i + 1]);
            F2 w00, w01, w10, w11;
            w00.f = *reinterpret_cast<const float2*>(&ws[i*32 + 2*o2]);
            w01.f = *reinterpret_cast<const float2*>(&ws[(i+1)*32 + 2*o2]);
            w10.f = *reinterpret_cast<const float2*>(&ws[1024 + i*32 + 2*o2]);
            w11.f = *reinterpret_cast<const float2*>(&ws[1024 + (i+1)*32 + 2*o2]);
            fma2(cx0, xv0, w00);
            fma2(cx1, xv1, w01);
            fma2(cy0, yv0, w10);
            fma2(cy1, yv1, w11);
        }
        const int o = 2*o2;
        float r0 = (cx0.f.x + cx1.f.x) + rinv*(cy0.f.x + cy1.f.x) + bsh[o];
        float r1 = (cx0.f.y + cx1.f.y) + rinv*(cy0.f.y + cy1.f.y) + bsh[o+1];
        *reinterpret_cast<float2*>(&out[(size_t)b*NN*CO + (size_t)n*CO + o]) = make_float2(r0, r1);
    }
}

// ---------------- launcher -------------------------------------------------
extern "C" void kernel_launch(void* const* d_in, const int* in_sizes, int n_in,
                              void* d_out, int out_size) {
    const float* x  = (const float*)d_in[0];
    const float* wp = (const float*)d_in[1];
    const float* bp = (const float*)d_in[2];
    const float* E  = (const float*)d_in[3];
    float* out = (float*)d_out;

    static bool attr_done = false;
    if (!attr_done) {
        cudaFuncSetAttribute(k_gemm, cudaFuncAttributeMaxDynamicSharedMemorySize, GSMEM);
        attr_done = true;
    }

    k_supports<<<NN/4, 256>>>(E);
    dim3 gt(NN/32, BB);
    k_tr<<<gt, 256>>>(x);
    dim3 gw(KIO/256, NN/128);
    k_wgen<<<gw, 256>>>(E, wp);
    dim3 gg(JTOT/256, NN/128);            // (4, 32) = 128 CTAs
    k_gemm<<<gg, 256, GSMEM>>>();
    k_out<<<NN, 256>>>(x, bp, E, out);
}